// round 8
// baseline (speedup 1.0000x reference)
#include <cuda_runtime.h>
#include <cuda_bf16.h>
#include <cuda_fp16.h>
#include <mma.h>
#include <cstdint>

using namespace nvcuda;

// Problem constants (fixed-shape problem)
#define NN 100000
#define NE 1600000
#define SCAN_NB 98                      // ceil(100000/1024)
#define EPS 1e-16f

// ---------------- scratch (device globals; no allocation allowed) ------------
__device__ __half2 g_h2[NN * 32];   // transformed features, fp16 (64 feats = 32 half2)
__device__ float g_agg[NN * 64];    // aggregated output of layer 1 (fp32)
__device__ float g_ssrc[NN];
__device__ float g_sdst[NN];
__device__ int   g_deg[NN];         // zero-init at load; re-zeroed by k_scan each run
__device__ int   g_cur[NN];         // exclusive prefix -> after scatter: inclusive
__device__ int   g_csrc[NE];
__device__ int   g_bsums[128];
__device__ int   g_done;            // k_scan completion counter (self-resetting)
__device__ int   g_epoch;           // k_scan epoch (monotonic across runs)

__device__ __forceinline__ float leaky(float v) {
    return fmaxf(v, 0.2f * v);   // NEG_SLOPE = 0.2
}

__device__ __forceinline__ float tanh_fast(float v) {
    asm("tanh.approx.f32 %0, %0;" : "+f"(v));
    return v;
}

// ---------------- histogram of dst (8 independent chains / thread) ----------
__global__ void k_hist(const int4* __restrict__ dst4) {
    const int Q = NE / 8;               // 200000 (int4 pairs)
    int t = blockIdx.x * blockDim.x + threadIdx.x;
    if (t < Q) {
        int4 d0 = dst4[t];
        int4 d1 = dst4[t + Q];
        atomicAdd(&g_deg[d0.x], 1);
        atomicAdd(&g_deg[d0.y], 1);
        atomicAdd(&g_deg[d0.z], 1);
        atomicAdd(&g_deg[d0.w], 1);
        atomicAdd(&g_deg[d1.x], 1);
        atomicAdd(&g_deg[d1.y], 1);
        atomicAdd(&g_deg[d1.z], 1);
        atomicAdd(&g_deg[d1.w], 1);
    }
}

// ---------------- single-kernel exclusive scan of deg -> g_cur ---------------
__global__ void __launch_bounds__(1024) k_scan() {
    __shared__ int swarp[32];
    __shared__ int sboff[128];
    int t = threadIdx.x, b = blockIdx.x;
    int lane = t & 31, wid = t >> 5;
    int idx = b * 1024 + t;

    int e0 = 0;
    if (t == 0) e0 = *(volatile int*)&g_epoch;   // read BEFORE publishing

    int v = (idx < NN) ? g_deg[idx] : 0;
    if (idx < NN) g_deg[idx] = 0;

    int x = v;
#pragma unroll
    for (int off = 1; off < 32; off <<= 1) {
        int y = __shfl_up_sync(~0u, x, off);
        if (lane >= off) x += y;
    }
    if (lane == 31) swarp[wid] = x;
    __syncthreads();
    if (wid == 0) {
        int s = swarp[lane];
#pragma unroll
        for (int off = 1; off < 32; off <<= 1) {
            int y = __shfl_up_sync(~0u, s, off);
            if (lane >= off) s += y;
        }
        swarp[lane] = s;
    }
    __syncthreads();
    int incl = x + (wid ? swarp[wid - 1] : 0);
    int ex = incl - v;
    int total = swarp[31];

    if (t == 0) {
        g_bsums[b] = total;
        __threadfence();
        int r = atomicAdd(&g_done, 1);
        if (r == SCAN_NB - 1) {
            g_done = 0;
            __threadfence();
            atomicAdd(&g_epoch, 1);
        }
        while (*(volatile int*)&g_epoch == e0) { }
    }
    __syncthreads();

    if (t < 128) sboff[t] = (t < SCAN_NB) ? g_bsums[t] : 0;
    __syncthreads();
    for (int off = 1; off < 128; off <<= 1) {
        int y = 0;
        if (t < 128) { y = sboff[t]; if (t >= off) y += sboff[t - off]; }
        __syncthreads();
        if (t < 128) sboff[t] = y;
        __syncthreads();
    }
    int boff = b ? sboff[b - 1] : 0;
    if (idx < NN) g_cur[idx] = ex + boff;
}

// ---------------- CSR scatter (8 independent chains / thread) ----------------
__global__ void k_scatter(const int4* __restrict__ src4, const int4* __restrict__ dst4) {
    const int Q = NE / 8;
    int t = blockIdx.x * blockDim.x + threadIdx.x;
    if (t < Q) {
        int4 s0 = src4[t];
        int4 d0 = dst4[t];
        int4 s1 = src4[t + Q];
        int4 d1 = dst4[t + Q];
        g_csrc[atomicAdd(&g_cur[d0.x], 1)] = s0.x;
        g_csrc[atomicAdd(&g_cur[d0.y], 1)] = s0.y;
        g_csrc[atomicAdd(&g_cur[d0.z], 1)] = s0.z;
        g_csrc[atomicAdd(&g_cur[d0.w], 1)] = s0.w;
        g_csrc[atomicAdd(&g_cur[d1.x], 1)] = s1.x;
        g_csrc[atomicAdd(&g_cur[d1.y], 1)] = s1.y;
        g_csrc[atomicAdd(&g_cur[d1.z], 1)] = s1.z;
        g_csrc[atomicAdd(&g_cur[d1.w], 1)] = s1.w;
    }
}

// ---------------- h = act(x) @ W via wmma + fused attention scores ----------
__global__ void __launch_bounds__(256) k_lin(
    const float* __restrict__ xin, const float* __restrict__ W,
    const float* __restrict__ b_in, int do_tanh, __half2* __restrict__ hout,
    const float* __restrict__ asrc, const float* __restrict__ adst)
{
    __shared__ __half Xh[64 * 72];
    __shared__ __half Wh[64 * 64];
    __shared__ float  Cs[64 * 72];
    int t = threadIdx.x;
    int row0 = blockIdx.x * 64;

    for (int i = t; i < 4096; i += 256) Wh[i] = __float2half(W[i]);
    for (int i = t; i < 4096; i += 256) {
        int r = i >> 6, c = i & 63;
        float v = 0.f;
        int gr = row0 + r;
        if (gr < NN) {
            v = xin[gr * 64 + c];
            if (do_tanh) v = tanh_fast(v + b_in[c]);
        }
        Xh[r * 72 + c] = __float2half(v);
    }
    __syncthreads();

    int w  = t >> 5;
    int wm = w & 3;     // row group (16 rows)
    int wn = w >> 2;    // col group (32 cols)
    wmma::fragment<wmma::accumulator, 16, 16, 16, float> c0, c1;
    wmma::fill_fragment(c0, 0.f);
    wmma::fill_fragment(c1, 0.f);
#pragma unroll
    for (int k0 = 0; k0 < 64; k0 += 16) {
        wmma::fragment<wmma::matrix_a, 16, 16, 16, __half, wmma::row_major> a;
        wmma::fragment<wmma::matrix_b, 16, 16, 16, __half, wmma::row_major> b0, b1;
        wmma::load_matrix_sync(a, Xh + wm * 16 * 72 + k0, 72);
        wmma::load_matrix_sync(b0, Wh + k0 * 64 + wn * 32, 64);
        wmma::load_matrix_sync(b1, Wh + k0 * 64 + wn * 32 + 16, 64);
        wmma::mma_sync(c0, a, b0, c0);
        wmma::mma_sync(c1, a, b1, c1);
    }
    wmma::store_matrix_sync(Cs + wm * 16 * 72 + wn * 32,      c0, 72, wmma::mem_row_major);
    wmma::store_matrix_sync(Cs + wm * 16 * 72 + wn * 32 + 16, c1, 72, wmma::mem_row_major);
    __syncthreads();

    for (int i = t; i < 2048; i += 256) {
        int r = i >> 5, c2 = i & 31;
        int gr = row0 + r;
        if (gr < NN)
            hout[gr * 32 + c2] =
                __floats2half2_rn(Cs[r * 72 + c2 * 2], Cs[r * 72 + c2 * 2 + 1]);
    }

    int r = t >> 2, q = t & 3;
    const float* crow = &Cs[r * 72 + q * 16];
    float ps = 0.f, pd = 0.f;
#pragma unroll
    for (int j = 0; j < 16; j++) {
        float hv = crow[j];
        ps += hv * asrc[q * 16 + j];
        pd += hv * adst[q * 16 + j];
    }
    ps += __shfl_down_sync(~0u, ps, 2, 4);
    ps += __shfl_down_sync(~0u, ps, 1, 4);
    pd += __shfl_down_sync(~0u, pd, 2, 4);
    pd += __shfl_down_sync(~0u, pd, 1, 4);
    if (q == 0 && row0 + r < NN) {
        g_ssrc[row0 + r] = ps;
        g_sdst[row0 + r] = pd;
    }
}

// ---------------- GAT aggregation: 2 nodes per warp (16 lanes each) ----------
// Each lane covers 4 features via uint2 (2 half2) loads; two independent edge
// streams per warp double the memory-level parallelism.
__global__ void __launch_bounds__(256) k_node(const __half2* __restrict__ h2,
                                              float* __restrict__ aggout,
                                              const float* __restrict__ b2,
                                              const float* __restrict__ Wl,
                                              const float* __restrict__ bl,
                                              float* __restrict__ out,
                                              int final_mode)
{
    __shared__ int   sS[8][2][16];
    __shared__ float sW[8][2][16];
    int warp = (blockIdx.x * blockDim.x + threadIdx.x) >> 5;
    int lane = threadIdx.x & 31;
    int w8   = (threadIdx.x >> 5) & 7;
    int half = lane >> 4;
    int sub  = lane & 15;
    int node = warp * 2 + half;
    if (node >= NN) return;        // NN even -> whole warp exits together
    int i = node;

    int r0 = (i > 0) ? __ldg(&g_cur[i - 1]) : 0;
    int r1 = __ldg(&g_cur[i]);
    float sd = g_sdst[i];

    float ex = __expf(fminf(leaky(g_ssrc[i] + sd), 60.f));   // self loop
    const uint2* hrow = (const uint2*)(h2 + i * 32);
    uint2 selfraw = __ldg(&hrow[sub]);
    float2 sf0 = __half22float2(*(__half2*)&selfraw.x);
    float2 sf1 = __half22float2(*(__half2*)&selfraw.y);
    float ax0 = ex * sf0.x, ay0 = ex * sf0.y;
    float ax1 = ex * sf1.x, ay1 = ex * sf1.y;
    float dl = 0.f;

    int nb = (r1 - r0 + 15) >> 4;
    int nbo = __shfl_xor_sync(~0u, nb, 16);
    int nbmax = max(nb, nbo);

    for (int b = 0; b < nbmax; b++) {
        int base = r0 + b * 16;
        int idx  = base + sub;
        int   s_l = 0;
        float w_l = 0.f;
        if (b < nb && idx < r1) {
            s_l = __ldg(&g_csrc[idx]);
            w_l = __expf(fminf(leaky(g_ssrc[s_l] + sd), 60.f));
        }
        sS[w8][half][sub] = s_l;
        sW[w8][half][sub] = w_l;
        dl += w_l;
        __syncwarp();
        int n = (b < nb) ? min(16, r1 - base) : 0;
        int j = 0;
        for (; j + 4 <= n; j += 4) {
            int   s0 = sS[w8][half][j],     s1 = sS[w8][half][j + 1];
            int   s2 = sS[w8][half][j + 2], s3 = sS[w8][half][j + 3];
            float w0 = sW[w8][half][j],     w1 = sW[w8][half][j + 1];
            float w2 = sW[w8][half][j + 2], w3 = sW[w8][half][j + 3];
            uint2 r0v = __ldg((const uint2*)(h2 + s0 * 32) + sub);
            uint2 r1v = __ldg((const uint2*)(h2 + s1 * 32) + sub);
            uint2 r2v = __ldg((const uint2*)(h2 + s2 * 32) + sub);
            uint2 r3v = __ldg((const uint2*)(h2 + s3 * 32) + sub);
            float2 a0 = __half22float2(*(__half2*)&r0v.x);
            float2 b0 = __half22float2(*(__half2*)&r0v.y);
            float2 a1 = __half22float2(*(__half2*)&r1v.x);
            float2 b1 = __half22float2(*(__half2*)&r1v.y);
            float2 a2 = __half22float2(*(__half2*)&r2v.x);
            float2 b2f = __half22float2(*(__half2*)&r2v.y);
            float2 a3 = __half22float2(*(__half2*)&r3v.x);
            float2 b3 = __half22float2(*(__half2*)&r3v.y);
            ax0 += w0 * a0.x + w1 * a1.x + w2 * a2.x + w3 * a3.x;
            ay0 += w0 * a0.y + w1 * a1.y + w2 * a2.y + w3 * a3.y;
            ax1 += w0 * b0.x + w1 * b1.x + w2 * b2f.x + w3 * b3.x;
            ay1 += w0 * b0.y + w1 * b1.y + w2 * b2f.y + w3 * b3.y;
        }
        for (; j < n; j++) {
            int   s0 = sS[w8][half][j];
            float w0 = sW[w8][half][j];
            uint2 rv = __ldg((const uint2*)(h2 + s0 * 32) + sub);
            float2 a0 = __half22float2(*(__half2*)&rv.x);
            float2 b0 = __half22float2(*(__half2*)&rv.y);
            ax0 += w0 * a0.x;
            ay0 += w0 * a0.y;
            ax1 += w0 * b0.x;
            ay1 += w0 * b0.y;
        }
        __syncwarp();
    }
    // reduce denom within 16-lane half (xor offsets stay inside the half)
#pragma unroll
    for (int o = 8; o; o >>= 1) dl += __shfl_xor_sync(~0u, dl, o);
    float inv = 1.f / (ex + dl + EPS);

    if (!final_mode) {
        *(float4*)&aggout[i * 64 + sub * 4] =
            make_float4(ax0 * inv, ay0 * inv, ax1 * inv, ay1 * inv);
    } else {
        float4 bv = *(const float4*)&b2[sub * 4];
        float4 wv = *(const float4*)&Wl[sub * 4];
        float s = (ax0 * inv + bv.x) * wv.x + (ay0 * inv + bv.y) * wv.y +
                  (ax1 * inv + bv.z) * wv.z + (ay1 * inv + bv.w) * wv.w;
#pragma unroll
        for (int o = 8; o; o >>= 1) s += __shfl_xor_sync(~0u, s, o);
        if (sub == 0) out[i] = s + bl[0];
    }
}

// ---------------- launcher ---------------------------------------------------
static cudaStream_t s_csr = nullptr;
static cudaEvent_t  s_evFork = nullptr, s_evJoin = nullptr;

extern "C" void kernel_launch(void* const* d_in, const int* in_sizes, int n_in,
                              void* d_out, int out_size)
{
    const float* x     = (const float*)d_in[0];
    const int*   eidx  = (const int*)d_in[1];
    const float* W1    = (const float*)d_in[2];
    const float* as1   = (const float*)d_in[3];
    const float* ad1   = (const float*)d_in[4];
    const float* b1    = (const float*)d_in[5];
    const float* W2    = (const float*)d_in[6];
    const float* as2   = (const float*)d_in[7];
    const float* ad2   = (const float*)d_in[8];
    const float* b2    = (const float*)d_in[9];
    const float* Wl    = (const float*)d_in[10];
    const float* bl    = (const float*)d_in[11];
    float* out = (float*)d_out;

    const int4* src4 = (const int4*)eidx;
    const int4* dst4 = (const int4*)(eidx + NE);

    __half2* h_ptr = nullptr;
    float* agg_ptr = nullptr;
    cudaGetSymbolAddress((void**)&h_ptr, g_h2);
    cudaGetSymbolAddress((void**)&agg_ptr, g_agg);

    if (!s_csr) {
        cudaStreamCreateWithFlags(&s_csr, cudaStreamNonBlocking);
        cudaEventCreateWithFlags(&s_evFork, cudaEventDisableTiming);
        cudaEventCreateWithFlags(&s_evJoin, cudaEventDisableTiming);
    }

    const int LIN_BLOCKS  = (NN + 63) / 64;          // 1563
    const int NODE_BLOCKS = (NN / 2 * 32 + 255) / 256; // 6250 (2 nodes/warp)
    const int E8_BLOCKS   = (NE / 8 + 255) / 256;    // 782

    // fork: CSR build runs concurrently with layer-1 linear
    cudaEventRecord(s_evFork, 0);
    cudaStreamWaitEvent(s_csr, s_evFork, 0);

    k_lin<<<LIN_BLOCKS, 256>>>(x, W1, nullptr, 0, h_ptr, as1, ad1);

    k_hist<<<E8_BLOCKS, 256, 0, s_csr>>>(dst4);
    k_scan<<<SCAN_NB, 1024, 0, s_csr>>>();
    k_scatter<<<E8_BLOCKS, 256, 0, s_csr>>>(src4, dst4);
    cudaEventRecord(s_evJoin, s_csr);
    cudaStreamWaitEvent(0, s_evJoin, 0);

    // layer-1 aggregation
    k_node<<<NODE_BLOCKS, 256>>>(h_ptr, agg_ptr, nullptr, nullptr, nullptr, nullptr, 0);
    // layer-2 linear (input = tanh(agg1 + b1))
    k_lin<<<LIN_BLOCKS, 256>>>(agg_ptr, W2, b1, 1, h_ptr, as2, ad2);
    // layer-2 aggregation + fused readout
    k_node<<<NODE_BLOCKS, 256>>>(h_ptr, nullptr, b2, Wl, bl, out, 1);
}